// round 7
// baseline (speedup 1.0000x reference)
#include <cuda_runtime.h>

// RGBuvHistBlock: x [8,3,256,256] f32 in [0,1]; bin_vals [64] = linspace(-1,1).
// hist[nc][b] = sum_p exp(-((2x-1)-b)^2/(2*0.02^2)), normalized per nc.
//
// R7: windowed scatter with (a) Gaussian recurrence (2 EX2 instead of 7:
// w_j = g * r^j * c_j), (b) float2-paired bins (4 LDS.64 + 4 STS.64 instead
// of 7+7 scalar): the 7-bin window always lies in 4 aligned bin-pairs.
// Per-thread private SMEM histograms -> no atomics, conflict-free.

#define NC_TOTAL   24
#define PIX_PER_NC 65536
#define HB         64
#define SPLITS     32
#define CHUNK      2048
#define NT         128
#define NPAIR      32            // 64 bins as 32 float2 pairs

// s = SA*(2x-1); weight = 2^{-(s-t)^2}; SA = sqrt(1250*log2(e))
#define SA    42.46608994f
#define SA2   84.93217988f
#define DS    1.34812984f        // scaled bin spacing
#define TWO_D 2.69625968f        // 2*DS
// c_j = 2^{-j^2*DS^2}
#define C1_  0.2837213f
#define C2_  6.479897e-3f
#define C3_  1.191316e-5f
#define C4_  1.763085e-9f
#define C5_  2.100399e-14f
#define C6_  2.014225e-20f
#define C7_  1.554903e-27f

__device__ float    g_part[NC_TOTAL * SPLITS * HB];
__device__ unsigned g_cnt[NC_TOTAL];

__device__ __forceinline__ float ex2f(float a) {
    float r;
    asm("ex2.approx.ftz.f32 %0, %1;" : "=f"(r) : "f"(a));
    return r;
}

__global__ __launch_bounds__(NT) void hist_fused_kernel(
    const float* __restrict__ x, const float* __restrict__ bin_vals,
    float* __restrict__ out)
{
    const int nc    = blockIdx.y;
    const int split = blockIdx.x;
    const int tid   = threadIdx.x;

    __shared__ float2 hist2[NPAIR * NT];   // 32KB: cell (pair p, thread t) = hist2[p*NT+t]
    __shared__ float  racc[NT];
    __shared__ float  ws[2];
    __shared__ int    slast;

    // Zero (16 STS.128 per thread).
    {
        float4* hz = reinterpret_cast<float4*>(hist2);
#pragma unroll
        for (int i = 0; i < (NPAIR * NT * 2 / 4) / NT; ++i)
            hz[tid + i * NT] = make_float4(0.f, 0.f, 0.f, 0.f);
    }
    __syncthreads();

    const float4* xp = reinterpret_cast<const float4*>(
        x + (size_t)nc * PIX_PER_NC + (size_t)split * CHUNK);

#pragma unroll 2
    for (int it = 0; it < CHUNK / (4 * NT); ++it) {
        float4 v = xp[tid + it * NT];
        float pv[4] = {v.x, v.y, v.z, v.w};
#pragma unroll
        for (int p = 0; p < 4; ++p) {
            float vf = pv[p];
            float sp = vf * SA2;                       // s' = s + SA, in [0, 2SA]
            int jc   = min(max(__float2int_rn(vf * 63.0f), 3), 60);
            int p0   = (jc - 3) >> 1;                  // first pair; bins [2p0, 2p0+7]
            float ds = fmaf((float)p0, -TWO_D, sp);    // dist to bin 2p0, scaled

            float g  = ex2f(-ds * ds);                 // 2^{-ds^2}
            float r  = ex2f(ds * TWO_D);               // 2^{2*D*ds}
            float r2 = r * r;
            float r3 = r2 * r;
            float r4 = r2 * r2;
            float gr4 = g * r4;
            float w0 = g;
            float w1 = g * (r  * C1_);
            float w2 = g * (r2 * C2_);
            float w3 = g * (r3 * C3_);
            float w4 = gr4 * C4_;
            float w5 = gr4 * (r  * C5_);
            float w6 = gr4 * (r2 * C6_);
            float w7 = gr4 * (r3 * C7_);

            float2* hp = hist2 + p0 * NT + tid;        // stride NT between pairs
            float2 h0 = hp[0 * NT];
            float2 h1 = hp[1 * NT];
            float2 h2 = hp[2 * NT];
            float2 h3 = hp[3 * NT];
            h0.x += w0; h0.y += w1;
            h1.x += w2; h1.y += w3;
            h2.x += w4; h2.y += w5;
            h3.x += w6; h3.y += w7;
            hp[0 * NT] = h0;
            hp[1 * NT] = h1;
            hp[2 * NT] = h2;
            hp[3 * NT] = h3;
        }
    }
    __syncthreads();

    // Block reduce over the float view: bin b cell c at word (b>>1)*2*NT + 2c + (b&1).
    // Thread (b, half) sums cells (half*64 + i + b) & 127: disjoint halves, complete.
    {
        const int b    = tid & (HB - 1);
        const int half = tid >> 6;
        const float* hb = reinterpret_cast<const float*>(hist2)
                        + (b >> 1) * (2 * NT) + (b & 1);
        float acc = 0.0f;
#pragma unroll 8
        for (int i = 0; i < 64; ++i) {
            int c = (half * 64 + i + b) & (NT - 1);
            acc += hb[2 * c];
        }
        racc[tid] = acc;
    }
    __syncthreads();

    if (tid < HB)
        g_part[((size_t)nc * SPLITS + split) * HB + tid] = racc[tid] + racc[tid + 64];
    __syncthreads();

    // Last block per nc reduces + normalizes.
    if (tid == 0) {
        __threadfence();
        unsigned old = atomicAdd(&g_cnt[nc], 1u);
        slast = (old == SPLITS - 1);
    }
    __syncthreads();
    if (!slast) return;
    __threadfence();

    float bsum = 0.0f;
    if (tid < HB) {
        const float* p = g_part + (size_t)nc * SPLITS * HB + tid;
#pragma unroll
        for (int sp = 0; sp < SPLITS; ++sp)
            bsum += p[(size_t)sp * HB];
    }
    float v = (tid < HB) ? bsum : 0.0f;
    float r = v;
#pragma unroll
    for (int o = 16; o; o >>= 1) r += __shfl_xor_sync(0xffffffffu, r, o);
    if (tid == 0)  ws[0] = r;
    if (tid == 32) ws[1] = r;
    __syncthreads();
    float tot = ws[0] + ws[1];

    if (tid < HB)
        out[nc * HB + tid] = v / (tot + 1e-8f);

    if (tid == 0) g_cnt[nc] = 0;   // reset for next graph replay
}

extern "C" void kernel_launch(void* const* d_in, const int* in_sizes, int n_in,
                              void* d_out, int out_size) {
    const float* x        = (const float*)d_in[0];
    const float* bin_vals = (const float*)d_in[1];
    float* out            = (float*)d_out;

    dim3 grid(SPLITS, NC_TOTAL);
    hist_fused_kernel<<<grid, NT>>>(x, bin_vals, out);
}